// round 6
// baseline (speedup 1.0000x reference)
#include <cuda_runtime.h>
#include <cstdint>

#define BATCH 8
#define NPRED 25500
#define NCLS  80
#define DPRED 85
#define KDET  300
#define FDIM  1920
#define HID   256
#define PERB_FEAT 1536000
#define CONF_T 0.1f
#define IOU_T  0.6f

// ---------------- device scratch (no allocations allowed) ----------------
__device__ __align__(128) float g_conf[BATCH * NPRED];
__device__ __align__(128) int   g_cls[BATCH * NPRED];
__device__ __align__(128) float g_boxes[BATCH * KDET * 4];
__device__ __align__(128) int   g_clstop[BATCH * KDET];
__device__ __align__(128) int   g_keep[BATCH * KDET];
__device__ __align__(128) float g_feat_t[BATCH * PERB_FEAT];   // (B, H, W, C) all 4 levels
__device__ __align__(128) float g_f[BATCH * KDET * FDIM];
__device__ __align__(128) float g_h1[BATCH * KDET * HID];

// ---------------- f32x2 helpers ----------------
__device__ __forceinline__ unsigned long long f2pack(float x, float y) {
    unsigned long long r;
    asm("mov.b64 %0, {%1,%2};" : "=l"(r) : "f"(x), "f"(y));
    return r;
}
__device__ __forceinline__ void f2unpack(unsigned long long v, float& x, float& y) {
    asm("mov.b64 {%0,%1}, %2;" : "=f"(x), "=f"(y) : "l"(v));
}
__device__ __forceinline__ void ffma2(unsigned long long& d, unsigned long long a, unsigned long long b) {
    asm("fma.rn.f32x2 %0, %1, %2, %0;" : "+l"(d) : "l"(a), "l"(b));
}

// ---------------- stage 1: conf = max(cls*obj), argmax (first index) ----------------
__global__ void conf_kernel(const float* __restrict__ preds) {
    int wg = (blockIdx.x * blockDim.x + threadIdx.x) >> 5;
    int lane = threadIdx.x & 31;
    if (wg >= BATCH * NPRED) return;
    const float* p = preds + (size_t)wg * DPRED;
    float obj = p[4];
    float best = -1.0f;
    int bidx = 0x7fffffff;
    for (int j = lane; j < NCLS; j += 32) {
        float s = __fmul_rn(p[5 + j], obj);   // exact single rounded multiply
        if (s > best) { best = s; bidx = j; }
    }
    #pragma unroll
    for (int off = 16; off; off >>= 1) {
        float ov = __shfl_down_sync(0xffffffffu, best, off);
        int   oi = __shfl_down_sync(0xffffffffu, bidx, off);
        if (ov > best || (ov == best && oi < bidx)) { best = ov; bidx = oi; }
    }
    if (lane == 0) {
        g_conf[wg] = (best > CONF_T) ? best : 0.0f;
        g_cls[wg]  = bidx;
    }
}

// ---------------- stage 2: exact top-k 300 per batch ----------------
// histogram-select candidates (>= cutoff bin), then bitonic sort packed keys
// key = (conf_bits << 32) | ~index  ->  descending sort == (conf desc, idx asc),
// matching jax.lax.top_k tie semantics exactly.
__global__ void topk_kernel(const float* __restrict__ preds) {
    int b = blockIdx.x;
    int tid = threadIdx.x;
    const float* conf = g_conf + (size_t)b * NPRED;

    __shared__ unsigned hist[2048];
    __shared__ int s_cb;
    __shared__ int s_cnt;
    __shared__ unsigned long long keys[4096];

    for (int i = tid; i < 2048; i += blockDim.x) hist[i] = 0;
    if (tid == 0) s_cnt = 0;
    __syncthreads();

    for (int n = tid; n < NPRED; n += blockDim.x) {
        float c = conf[n];
        int bin = min((int)(c * 2048.0f), 2047);
        atomicAdd(&hist[bin], 1u);
    }
    __syncthreads();

    if (tid == 0) {
        unsigned acc = 0; int cb = 1;
        for (int i = 2047; i >= 1; --i) {
            acc += hist[i];
            if (acc >= KDET) { cb = i; break; }
        }
        s_cb = cb;
    }
    for (int i = tid; i < 4096; i += blockDim.x) keys[i] = 0ULL;
    __syncthreads();

    int cb = s_cb;
    for (int n = tid; n < NPRED; n += blockDim.x) {
        float c = conf[n];
        int bin = min((int)(c * 2048.0f), 2047);
        if (bin >= cb) {
            int pos = atomicAdd(&s_cnt, 1);
            if (pos < 4096)
                keys[pos] = ((unsigned long long)__float_as_uint(c) << 32) |
                            (unsigned)(~(unsigned)n);
        }
    }
    __syncthreads();

    // bitonic sort ascending, 4096 keys
    for (int k2 = 2; k2 <= 4096; k2 <<= 1) {
        for (int j = k2 >> 1; j > 0; j >>= 1) {
            for (int i = tid; i < 4096; i += blockDim.x) {
                int ixj = i ^ j;
                if (ixj > i) {
                    unsigned long long a = keys[i], c2 = keys[ixj];
                    bool asc = ((i & k2) == 0);
                    if ((a > c2) == asc) { keys[i] = c2; keys[ixj] = a; }
                }
            }
            __syncthreads();
        }
    }

    if (tid < KDET) {
        unsigned long long key = keys[4095 - tid];
        int o = b * KDET + tid;
        if (key == 0ULL) {                     // fewer than 300 candidates (padding)
            g_boxes[o * 4 + 0] = 0.f; g_boxes[o * 4 + 1] = 0.f;
            g_boxes[o * 4 + 2] = 0.f; g_boxes[o * 4 + 3] = 0.f;
            g_clstop[o] = 0;
            g_keep[o] = 0;
        } else {
            float v = __uint_as_float((unsigned)(key >> 32));
            unsigned n = ~(unsigned)(key & 0xFFFFFFFFu);
            const float* p = preds + ((size_t)b * NPRED + n) * DPRED;
            // reference: xy - wh/2, xy + wh/2 (unfused: div then sub/add)
            float cx = p[0], cy = p[1], w = p[2], h = p[3];
            float hw2 = __fmul_rn(w, 0.5f);   // w/2 exact (mul by 0.5 == div by 2)
            float hh2 = __fmul_rn(h, 0.5f);
            g_boxes[o * 4 + 0] = __fsub_rn(cx, hw2);
            g_boxes[o * 4 + 1] = __fsub_rn(cy, hh2);
            g_boxes[o * 4 + 2] = __fadd_rn(cx, hw2);
            g_boxes[o * 4 + 3] = __fadd_rn(cy, hh2);
            g_clstop[o] = g_cls[(size_t)b * NPRED + n];
            g_keep[o]   = (v > CONF_T) ? 1 : 0;
        }
    }
}

// ---------------- stage 3: greedy NMS (class-offset boxes), unfused IoU ----------------
__global__ void nms_kernel() {
    int b = blockIdx.x;
    int tid = threadIdx.x;
    __shared__ float sx1[KDET], sy1[KDET], sx2[KDET], sy2[KDET], sar[KDET];
    __shared__ int skeep[KDET];
    if (tid < KDET) {
        int o = b * KDET + tid;
        float off = __fmul_rn((float)g_clstop[o], 4096.0f);
        float x1 = __fadd_rn(g_boxes[o * 4 + 0], off);
        float y1 = __fadd_rn(g_boxes[o * 4 + 1], off);
        float x2 = __fadd_rn(g_boxes[o * 4 + 2], off);
        float y2 = __fadd_rn(g_boxes[o * 4 + 3], off);
        sx1[tid] = x1; sy1[tid] = y1; sx2[tid] = x2; sy2[tid] = y2;
        sar[tid] = __fmul_rn(__fsub_rn(x2, x1), __fsub_rn(y2, y1));
        skeep[tid] = g_keep[o];
    }
    __syncthreads();
    for (int i = 0; i < KDET - 1; ++i) {
        if (skeep[i]) {                 // uniform branch (same smem value block-wide)
            if (tid > i && tid < KDET && skeep[tid]) {
                float lx = fmaxf(sx1[i], sx1[tid]);
                float ly = fmaxf(sy1[i], sy1[tid]);
                float rx = fminf(sx2[i], sx2[tid]);
                float ry = fminf(sy2[i], sy2[tid]);
                float w = fmaxf(__fsub_rn(rx, lx), 0.f);
                float h = fmaxf(__fsub_rn(ry, ly), 0.f);
                float inter = __fmul_rn(w, h);
                float den = __fadd_rn(__fsub_rn(__fadd_rn(sar[i], sar[tid]), inter), 1e-7f);
                float iou = __fdiv_rn(inter, den);
                if (iou > IOU_T) skeep[tid] = 0;
            }
            __syncthreads();
        }
    }
    if (tid < KDET) g_keep[b * KDET + tid] = skeep[tid];
}

// ---------------- stage 4: transpose features (B,C,H,W) -> (B,H,W,C) ----------------
__global__ void transpose_kernel(const float* __restrict__ in, int C, int HW, int outOff) {
    __shared__ float tile[32][33];
    int b = blockIdx.z;
    int hw0 = blockIdx.x * 32, c0 = blockIdx.y * 32;
    const float* src = in + (size_t)b * C * HW;
    float* dst = g_feat_t + (size_t)b * PERB_FEAT + outOff;
    int x = hw0 + threadIdx.x;
    for (int i = threadIdx.y; i < 32; i += 8) {
        int c = c0 + i;
        if (c < C && x < HW) tile[i][threadIdx.x] = src[(size_t)c * HW + x];
    }
    __syncthreads();
    int c = c0 + threadIdx.x;
    for (int i = threadIdx.y; i < 32; i += 8) {
        int hw = hw0 + i;
        if (hw < HW && c < C) dst[(size_t)hw * C + c] = tile[threadIdx.x][i];
    }
}

// ---------------- stage 5: ROI align 1x1 over 4 levels, unfused coords ----------------
__global__ void roi_kernel() {
    int det = blockIdx.x, b = blockIdx.y;
    int o = b * KDET + det;
    int tid = threadIdx.x;
    float* frow = g_f + (size_t)o * FDIM;
    if (!g_keep[o]) {   // row multiplied by keep=0 in the end; zero f so GEMM is benign
        float4 z = make_float4(0.f, 0.f, 0.f, 0.f);
        for (int u = tid; u < FDIM / 4; u += blockDim.x) ((float4*)frow)[u] = z;
        return;
    }
    __shared__ int   s_off[4][4][4];
    __shared__ float s_w[4][4][4];
    if (tid < 4) {
        int l = tid;
        float sc = 0.125f / (float)(1 << l);     // 1/8, 1/16, 1/32, 1/64 (exact powers of 2)
        int H = 80 >> l, W = 80 >> l;
        int C = 128 << l;
        // reference: b = boxes * scale; w = max(b2-b0, 1); xs = b0 + off*(w/2)
        float bx0 = __fmul_rn(g_boxes[o * 4 + 0], sc);
        float by0 = __fmul_rn(g_boxes[o * 4 + 1], sc);
        float bx2 = __fmul_rn(g_boxes[o * 4 + 2], sc);
        float by2 = __fmul_rn(g_boxes[o * 4 + 3], sc);
        float w = fmaxf(__fsub_rn(bx2, bx0), 1.f);
        float h = fmaxf(__fsub_rn(by2, by0), 1.f);
        float w2 = __fmul_rn(w, 0.5f);   // w/2.0 (mul by exact 0.5 == div)
        float h2 = __fmul_rn(h, 0.5f);
        float xs[2] = { __fadd_rn(bx0, __fmul_rn(0.5f, w2)), __fadd_rn(bx0, __fmul_rn(1.5f, w2)) };
        float ys[2] = { __fadd_rn(by0, __fmul_rn(0.5f, h2)), __fadd_rn(by0, __fmul_rn(1.5f, h2)) };
        for (int p = 0; p < 4; ++p) {
            float y = fminf(fmaxf(ys[p >> 1], 0.f), (float)(H - 1));
            float x = fminf(fmaxf(xs[p & 1], 0.f), (float)(W - 1));
            int y0 = (int)floorf(y), x0 = (int)floorf(x);
            int y1 = min(y0 + 1, H - 1), x1 = min(x0 + 1, W - 1);
            float ly = __fsub_rn(y, (float)y0);
            float lx = __fsub_rn(x, (float)x0);
            float oly = __fsub_rn(1.f, ly);
            float olx = __fsub_rn(1.f, lx);
            s_off[l][p][0] = (y0 * W + x0) * C;
            s_off[l][p][1] = (y0 * W + x1) * C;
            s_off[l][p][2] = (y1 * W + x0) * C;
            s_off[l][p][3] = (y1 * W + x1) * C;
            s_w[l][p][0] = __fmul_rn(oly, olx);
            s_w[l][p][1] = __fmul_rn(oly, lx);
            s_w[l][p][2] = __fmul_rn(ly, olx);
            s_w[l][p][3] = __fmul_rn(ly, lx);
        }
    }
    __syncthreads();

    const float* FTb = g_feat_t + (size_t)b * PERB_FEAT;
    const int lvlOff[4] = {0, 819200, 1228800, 1433600};
    for (int u = tid; u < FDIM / 4; u += blockDim.x) {   // 480 float4 lanes, warp-uniform level
        int l, start;
        if (u < 32)       { l = 0; start = 0;   }
        else if (u < 96)  { l = 1; start = 32;  }
        else if (u < 224) { l = 2; start = 96;  }
        else              { l = 3; start = 224; }
        const float* FT = FTb + lvlOff[l] + (u - start) * 4;
        // reference: per-point bilinear sum of 4 rounded products, mean over 4 points
        float ax = 0.f, ay = 0.f, az = 0.f, aw = 0.f;
        #pragma unroll
        for (int p = 0; p < 4; ++p) {
            float vx = 0.f, vy = 0.f, vz = 0.f, vw = 0.f;
            #pragma unroll
            for (int t = 0; t < 4; ++t) {
                float4 v = *(const float4*)(FT + s_off[l][p][t]);
                float wv = s_w[l][p][t];
                vx = __fadd_rn(vx, __fmul_rn(wv, v.x));
                vy = __fadd_rn(vy, __fmul_rn(wv, v.y));
                vz = __fadd_rn(vz, __fmul_rn(wv, v.z));
                vw = __fadd_rn(vw, __fmul_rn(wv, v.w));
            }
            ax = __fadd_rn(ax, vx); ay = __fadd_rn(ay, vy);
            az = __fadd_rn(az, vz); aw = __fadd_rn(aw, vw);
        }
        float4 acc;
        acc.x = __fmul_rn(ax, 0.25f); acc.y = __fmul_rn(ay, 0.25f);
        acc.z = __fmul_rn(az, 0.25f); acc.w = __fmul_rn(aw, 0.25f);
        *(float4*)(frow + u * 4) = acc;
    }
}

// ---------------- stage 6: fp32 GEMM (f32x2 packed FMA) + bias + leaky ----------------
__global__ void __launch_bounds__(256) gemm_kernel(
    const float* __restrict__ Wm, const float* __restrict__ bias,
    float* __restrict__ outp, int which, int M, int Kd, int ldc, int col_off, int mulkeep)
{
    const float* A = which ? g_h1 : g_f;
    float* Cp = which ? outp : g_h1;
    __shared__ float As[16][64];
    __shared__ float Bs[16][64];
    int tid = threadIdx.x;
    int m0 = blockIdx.y << 6, n0 = blockIdx.x << 6;
    int ty = tid >> 4, tx = tid & 15;
    unsigned long long acc[4][2];
    #pragma unroll
    for (int i = 0; i < 4; ++i)
        #pragma unroll
        for (int j = 0; j < 2; ++j) acc[i][j] = f2pack(0.f, 0.f);

    int arow = m0 + (tid >> 2);
    int acol = (tid & 3) << 2;
    int asr  = tid >> 2;
    const float* aptr = A + (size_t)arow * Kd + acol;
    const float* bptr = Wm + (size_t)(tid >> 4) * HID + n0 + ((tid & 15) << 2);

    for (int kk = 0; kk < Kd; kk += 16) {
        float4 av = make_float4(0.f, 0.f, 0.f, 0.f);
        if (arow < M) av = *(const float4*)aptr;
        aptr += 16;
        As[acol + 0][asr] = av.x;
        As[acol + 1][asr] = av.y;
        As[acol + 2][asr] = av.z;
        As[acol + 3][asr] = av.w;
        *(float4*)&Bs[tid >> 4][(tid & 15) << 2] = *(const float4*)bptr;
        bptr += 16 * HID;
        __syncthreads();
        #pragma unroll
        for (int k = 0; k < 16; ++k) {
            float4 a = *(const float4*)&As[k][ty << 2];
            unsigned long long b01 = *(const unsigned long long*)&Bs[k][(tx << 2)];
            unsigned long long b23 = *(const unsigned long long*)&Bs[k][(tx << 2) + 2];
            unsigned long long a0 = f2pack(a.x, a.x);
            unsigned long long a1 = f2pack(a.y, a.y);
            unsigned long long a2 = f2pack(a.z, a.z);
            unsigned long long a3 = f2pack(a.w, a.w);
            ffma2(acc[0][0], a0, b01); ffma2(acc[0][1], a0, b23);
            ffma2(acc[1][0], a1, b01); ffma2(acc[1][1], a1, b23);
            ffma2(acc[2][0], a2, b01); ffma2(acc[2][1], a2, b23);
            ffma2(acc[3][0], a3, b01); ffma2(acc[3][1], a3, b23);
        }
        __syncthreads();
    }
    #pragma unroll
    for (int i = 0; i < 4; ++i) {
        int m = m0 + (ty << 2) + i;
        if (m >= M) continue;
        float kf = 1.f;
        if (mulkeep) kf = g_keep[m] ? 1.f : 0.f;
        float* crow = Cp + (size_t)m * ldc + col_off + n0 + (tx << 2);
        #pragma unroll
        for (int j = 0; j < 2; ++j) {
            float v0, v1;
            f2unpack(acc[i][j], v0, v1);
            int nc = n0 + (tx << 2) + (j << 1);
            v0 = __fadd_rn(v0, bias[nc]);
            v1 = __fadd_rn(v1, bias[nc + 1]);
            v0 = (v0 >= 0.f) ? v0 : __fmul_rn(v0, 0.01f);
            v1 = (v1 >= 0.f) ? v1 : __fmul_rn(v1, 0.01f);
            crow[(j << 1)]     = __fmul_rn(v0, kf);
            crow[(j << 1) + 1] = __fmul_rn(v1, kf);
        }
    }
}

// ---------------- stage 7: rescale + write bb columns (unfused) ----------------
__global__ void bbox_kernel(const float* __restrict__ orig_hw, float* __restrict__ out) {
    int idx = blockIdx.x * blockDim.x + threadIdx.x;
    if (idx >= BATCH * KDET) return;
    int b = idx / KDET;
    float oh = orig_hw[b * 2 + 0], ow = orig_hw[b * 2 + 1];
    // reference: gain = min(hw/hw0); pad = (hw - hw0*gain)/2
    float gain = fminf(__fdiv_rn(640.f, oh), __fdiv_rn(640.f, ow));
    float padx = __fmul_rn(__fsub_rn(640.f, __fmul_rn(ow, gain)), 0.5f);
    float pady = __fmul_rn(__fsub_rn(640.f, __fmul_rn(oh, gain)), 0.5f);
    float kf = g_keep[idx] ? 1.f : 0.f;
    const float* bx = g_boxes + (size_t)idx * 4;
    float x1 = fminf(fmaxf(__fdiv_rn(__fsub_rn(bx[0], padx), gain), 0.f), ow);
    float y1 = fminf(fmaxf(__fdiv_rn(__fsub_rn(bx[1], pady), gain), 0.f), oh);
    float x2 = fminf(fmaxf(__fdiv_rn(__fsub_rn(bx[2], padx), gain), 0.f), ow);
    float y2 = fminf(fmaxf(__fdiv_rn(__fsub_rn(bx[3], pady), gain), 0.f), oh);
    float* orow = out + (size_t)idx * 260;
    orow[0] = __fmul_rn(__fdiv_rn(x1, ow), kf);
    orow[1] = __fmul_rn(__fdiv_rn(y1, oh), kf);
    orow[2] = __fmul_rn(__fdiv_rn(x2, ow), kf);
    orow[3] = __fmul_rn(__fdiv_rn(y2, oh), kf);
}

// ---------------- launch ----------------
extern "C" void kernel_launch(void* const* d_in, const int* in_sizes, int n_in,
                              void* d_out, int out_size) {
    (void)in_sizes; (void)n_in; (void)out_size;
    const float* preds   = (const float*)d_in[0];
    const float* feat1   = (const float*)d_in[1];
    const float* feat2   = (const float*)d_in[2];
    const float* feat3   = (const float*)d_in[3];
    const float* feat4   = (const float*)d_in[4];
    const float* orig_hw = (const float*)d_in[5];
    const float* W1      = (const float*)d_in[6];
    const float* b1      = (const float*)d_in[7];
    const float* W2      = (const float*)d_in[8];
    const float* b2      = (const float*)d_in[9];
    float* out = (float*)d_out;

    // conf/argmax: 1 warp per prediction
    conf_kernel<<<(BATCH * NPRED) / 8, 256>>>(preds);

    // feature transposes (independent of conf/topk; serialized on stream for now)
    transpose_kernel<<<dim3(200, 4, BATCH),  dim3(32, 8)>>>(feat1, 128,  6400, 0);
    transpose_kernel<<<dim3(50, 8, BATCH),   dim3(32, 8)>>>(feat2, 256,  1600, 819200);
    transpose_kernel<<<dim3(13, 16, BATCH),  dim3(32, 8)>>>(feat3, 512,  400,  1228800);
    transpose_kernel<<<dim3(4, 32, BATCH),   dim3(32, 8)>>>(feat4, 1024, 100,  1433600);

    topk_kernel<<<BATCH, 1024>>>(preds);
    nms_kernel<<<BATCH, 320>>>();

    roi_kernel<<<dim3(KDET, BATCH), 256>>>();

    gemm_kernel<<<dim3(4, 38), 256>>>(W1, b1, nullptr, 0, BATCH * KDET, FDIM, HID, 0, 0);
    gemm_kernel<<<dim3(4, 38), 256>>>(W2, b2, out,     1, BATCH * KDET, HID,  260, 4, 1);

    bbox_kernel<<<(BATCH * KDET + 255) / 256, 256>>>(orig_hw, out);
}

// round 16
// speedup vs baseline: 1.1803x; 1.1803x over previous
#include <cuda_runtime.h>
#include <cstdint>

#define BATCH 8
#define NPRED 25500
#define NCLS  80
#define DPRED 85
#define KDET  300
#define FDIM  1920
#define HID   256
#define PERB_FEAT 1536000
#define CONF_T 0.1f
#define IOU_T  0.6f
#define PREDS_PER_BLK 48

// ---------------- device scratch (no allocations allowed) ----------------
__device__ __align__(128) float g_conf[BATCH * NPRED];
__device__ __align__(128) int   g_cls[BATCH * NPRED];
__device__ __align__(128) float g_boxes[BATCH * KDET * 4];
__device__ __align__(128) int   g_clstop[BATCH * KDET];
__device__ __align__(128) int   g_keep[BATCH * KDET];
__device__ __align__(128) float g_feat_t[BATCH * PERB_FEAT];   // (B, H, W, C) all 4 levels
__device__ __align__(128) float g_f[BATCH * KDET * FDIM];
__device__ __align__(128) float g_h1[BATCH * KDET * HID];

// ---------------- f32x2 helpers ----------------
__device__ __forceinline__ unsigned long long f2pack(float x, float y) {
    unsigned long long r;
    asm("mov.b64 %0, {%1,%2};" : "=l"(r) : "f"(x), "f"(y));
    return r;
}
__device__ __forceinline__ void f2unpack(unsigned long long v, float& x, float& y) {
    asm("mov.b64 {%0,%1}, %2;" : "=f"(x), "=f"(y) : "l"(v));
}
__device__ __forceinline__ void ffma2(unsigned long long& d, unsigned long long a, unsigned long long b) {
    asm("fma.rn.f32x2 %0, %1, %2, %0;" : "+l"(d) : "l"(a), "l"(b));
}

// ---------------- stage 1: conf/argmax, smem-staged coalesced loads ----------------
// 48 preds per block = 4080 floats = 16320 bytes (16B-aligned chunk per block).
__global__ void __launch_bounds__(256) conf_kernel(const float* __restrict__ preds) {
    __shared__ float sp[PREDS_PER_BLK * DPRED];
    int tid = threadIdx.x;
    const float4* src = (const float4*)(preds + (size_t)blockIdx.x * (PREDS_PER_BLK * DPRED));
    float4* dst4 = (float4*)sp;
    #pragma unroll
    for (int u = tid; u < PREDS_PER_BLK * DPRED / 4; u += 256) dst4[u] = src[u];
    __syncthreads();
    int w = tid >> 5, lane = tid & 31;
    #pragma unroll
    for (int k = 0; k < 6; ++k) {
        int p = w * 6 + k;
        const float* row = sp + p * DPRED;
        float obj = row[4];
        float best = -1.0f;
        int bidx = 0x7fffffff;
        for (int j = lane; j < NCLS; j += 32) {
            float s = __fmul_rn(row[5 + j], obj);   // exact single rounded multiply
            if (s > best) { best = s; bidx = j; }
        }
        #pragma unroll
        for (int off = 16; off; off >>= 1) {
            float ov = __shfl_down_sync(0xffffffffu, best, off);
            int   oi = __shfl_down_sync(0xffffffffu, bidx, off);
            if (ov > best || (ov == best && oi < bidx)) { best = ov; bidx = oi; }
        }
        if (lane == 0) {
            int g = blockIdx.x * PREDS_PER_BLK + p;
            g_conf[g] = (best > CONF_T) ? best : 0.0f;
            g_cls[g]  = bidx;
        }
    }
}

// ---------------- stage 2: exact top-k 300 per batch ----------------
// histogram-select candidates, then bitonic sort; adaptive 512-key fast path.
// key = (conf_bits << 32) | ~index  ->  descending == (conf desc, idx asc).
__global__ void topk_kernel(const float* __restrict__ preds) {
    int b = blockIdx.x;
    int tid = threadIdx.x;
    const float* conf = g_conf + (size_t)b * NPRED;

    __shared__ unsigned hist[2048];
    __shared__ int s_cb;
    __shared__ int s_cnt;
    __shared__ unsigned long long keys[4096];

    for (int i = tid; i < 2048; i += blockDim.x) hist[i] = 0;
    if (tid == 0) s_cnt = 0;
    __syncthreads();

    for (int n = tid; n < NPRED; n += blockDim.x) {
        float c = conf[n];
        int bin = min((int)(c * 2048.0f), 2047);
        atomicAdd(&hist[bin], 1u);
    }
    __syncthreads();

    if (tid == 0) {
        unsigned acc = 0; int cb = 1;
        for (int i = 2047; i >= 1; --i) {
            acc += hist[i];
            if (acc >= KDET) { cb = i; break; }
        }
        s_cb = cb;
    }
    for (int i = tid; i < 4096; i += blockDim.x) keys[i] = 0ULL;
    __syncthreads();

    int cb = s_cb;
    for (int n = tid; n < NPRED; n += blockDim.x) {
        float c = conf[n];
        int bin = min((int)(c * 2048.0f), 2047);
        if (bin >= cb) {
            int pos = atomicAdd(&s_cnt, 1);
            if (pos < 4096)
                keys[pos] = ((unsigned long long)__float_as_uint(c) << 32) |
                            (unsigned)(~(unsigned)n);
        }
    }
    __syncthreads();

    // bitonic sort ascending; zero-padded keys sort below real candidates,
    // so sorting the smallest power-of-2 >= cnt gives identical top-300.
    int nsort = (s_cnt <= 512) ? 512 : 4096;
    for (int k2 = 2; k2 <= nsort; k2 <<= 1) {
        for (int j = k2 >> 1; j > 0; j >>= 1) {
            for (int i = tid; i < nsort; i += blockDim.x) {
                int ixj = i ^ j;
                if (ixj > i) {
                    unsigned long long a = keys[i], c2 = keys[ixj];
                    bool asc = ((i & k2) == 0);
                    if ((a > c2) == asc) { keys[i] = c2; keys[ixj] = a; }
                }
            }
            __syncthreads();
        }
    }

    if (tid < KDET) {
        unsigned long long key = keys[nsort - 1 - tid];
        int o = b * KDET + tid;
        if (key == 0ULL) {                     // fewer than 300 candidates (padding)
            g_boxes[o * 4 + 0] = 0.f; g_boxes[o * 4 + 1] = 0.f;
            g_boxes[o * 4 + 2] = 0.f; g_boxes[o * 4 + 3] = 0.f;
            g_clstop[o] = 0;
            g_keep[o] = 0;
        } else {
            float v = __uint_as_float((unsigned)(key >> 32));
            unsigned n = ~(unsigned)(key & 0xFFFFFFFFu);
            const float* p = preds + ((size_t)b * NPRED + n) * DPRED;
            float cx = p[0], cy = p[1], w = p[2], h = p[3];
            float hw2 = __fmul_rn(w, 0.5f);
            float hh2 = __fmul_rn(h, 0.5f);
            g_boxes[o * 4 + 0] = __fsub_rn(cx, hw2);
            g_boxes[o * 4 + 1] = __fsub_rn(cy, hh2);
            g_boxes[o * 4 + 2] = __fadd_rn(cx, hw2);
            g_boxes[o * 4 + 3] = __fadd_rn(cy, hh2);
            g_clstop[o] = g_cls[(size_t)b * NPRED + n];
            g_keep[o]   = (v > CONF_T) ? 1 : 0;
        }
    }
}

// ---------------- stage 3: NMS via suppression bitmask + single-warp scan ----------------
// sup[i] precomputed fully parallel; greedy scan has identical semantics to
// the reference fori_loop: sup = keep[i] & (iou[i] > T) & (idx > i).
#define KWORDS 10
__global__ void __launch_bounds__(320) nms_kernel() {
    int b = blockIdx.x;
    int tid = threadIdx.x;
    __shared__ float sx1[KDET], sy1[KDET], sx2[KDET], sy2[KDET], sar[KDET];
    __shared__ unsigned sup[KDET][KWORDS];
    __shared__ unsigned keepw[KWORDS];
    if (tid < KDET) {
        int o = b * KDET + tid;
        float off = __fmul_rn((float)g_clstop[o], 4096.0f);
        float x1 = __fadd_rn(g_boxes[o * 4 + 0], off);
        float y1 = __fadd_rn(g_boxes[o * 4 + 1], off);
        float x2 = __fadd_rn(g_boxes[o * 4 + 2], off);
        float y2 = __fadd_rn(g_boxes[o * 4 + 3], off);
        sx1[tid] = x1; sy1[tid] = y1; sx2[tid] = x2; sy2[tid] = y2;
        sar[tid] = __fmul_rn(__fsub_rn(x2, x1), __fsub_rn(y2, y1));
    }
    if (tid < KWORDS) {
        unsigned m = 0;
        for (int j = 0; j < 32; ++j) {
            int idx = (tid << 5) + j;
            if (idx < KDET && g_keep[b * KDET + idx]) m |= (1u << j);
        }
        keepw[tid] = m;
    }
    __syncthreads();

    // precompute suppression rows (IoU unfused, identical op order to before)
    for (int i = tid; i < KDET; i += blockDim.x) {
        unsigned row[KWORDS];
        #pragma unroll
        for (int w2 = 0; w2 < KWORDS; ++w2) row[w2] = 0;
        float ix1 = sx1[i], iy1 = sy1[i], ix2 = sx2[i], iy2 = sy2[i], iar = sar[i];
        for (int j = i + 1; j < KDET; ++j) {
            float lx = fmaxf(ix1, sx1[j]);
            float ly = fmaxf(iy1, sy1[j]);
            float rx = fminf(ix2, sx2[j]);
            float ry = fminf(iy2, sy2[j]);
            float w = fmaxf(__fsub_rn(rx, lx), 0.f);
            float h = fmaxf(__fsub_rn(ry, ly), 0.f);
            float inter = __fmul_rn(w, h);
            float den = __fadd_rn(__fsub_rn(__fadd_rn(iar, sar[j]), inter), 1e-7f);
            float iou = __fdiv_rn(inter, den);
            if (iou > IOU_T) row[j >> 5] |= (1u << (j & 31));
        }
        #pragma unroll
        for (int w2 = 0; w2 < KWORDS; ++w2) sup[i][w2] = row[w2];
    }
    __syncthreads();

    // serial greedy scan: warp 0, lane w owns keep word w. No block barriers.
    if (tid < 32) {
        unsigned kw = (tid < KWORDS) ? keepw[tid] : 0u;
        for (int i = 0; i < KDET; ++i) {
            unsigned wsrc = __shfl_sync(0xffffffffu, kw, i >> 5);
            if ((wsrc >> (i & 31)) & 1u) {
                if (tid < KWORDS) kw &= ~sup[i][tid];
            }
        }
        if (tid < KWORDS) keepw[tid] = kw;
    }
    __syncthreads();
    if (tid < KDET) g_keep[b * KDET + tid] = (keepw[tid >> 5] >> (tid & 31)) & 1u;
}

// ---------------- stage 4: fused transpose, all 4 levels, (B,C,H,W)->(B,H,W,C) ----------------
__global__ void transpose_all(const float* __restrict__ f1, const float* __restrict__ f2,
                              const float* __restrict__ f3, const float* __restrict__ f4) {
    __shared__ float tile[32][33];
    int bx = blockIdx.x, b = blockIdx.y;
    const float* src; int C, HW, off, hwT;
    if (bx < 800)       { src = f1; C = 128;  HW = 6400; off = 0;       hwT = 200; }
    else if (bx < 1200) { bx -= 800;  src = f2; C = 256;  HW = 1600; off = 819200;  hwT = 50; }
    else if (bx < 1408) { bx -= 1200; src = f3; C = 512;  HW = 400;  off = 1228800; hwT = 13; }
    else                { bx -= 1408; src = f4; C = 1024; HW = 100;  off = 1433600; hwT = 4; }
    int hw0 = (bx % hwT) * 32, c0 = (bx / hwT) * 32;
    src += (size_t)b * C * HW;
    float* dst = g_feat_t + (size_t)b * PERB_FEAT + off;
    int x = hw0 + threadIdx.x;
    for (int i = threadIdx.y; i < 32; i += 8) {
        int c = c0 + i;
        if (c < C && x < HW) tile[i][threadIdx.x] = src[(size_t)c * HW + x];
    }
    __syncthreads();
    int c = c0 + threadIdx.x;
    for (int i = threadIdx.y; i < 32; i += 8) {
        int hw = hw0 + i;
        if (hw < HW && c < C) dst[(size_t)hw * C + c] = tile[threadIdx.x][i];
    }
}

// ---------------- stage 5: ROI align 1x1 over 4 levels, unfused coords ----------------
__global__ void roi_kernel() {
    int det = blockIdx.x, b = blockIdx.y;
    int o = b * KDET + det;
    int tid = threadIdx.x;
    float* frow = g_f + (size_t)o * FDIM;
    if (!g_keep[o]) {
        float4 z = make_float4(0.f, 0.f, 0.f, 0.f);
        for (int u = tid; u < FDIM / 4; u += blockDim.x) ((float4*)frow)[u] = z;
        return;
    }
    __shared__ int   s_off[4][4][4];
    __shared__ float s_w[4][4][4];
    if (tid < 4) {
        int l = tid;
        float sc = 0.125f / (float)(1 << l);
        int H = 80 >> l, W = 80 >> l;
        int C = 128 << l;
        float bx0 = __fmul_rn(g_boxes[o * 4 + 0], sc);
        float by0 = __fmul_rn(g_boxes[o * 4 + 1], sc);
        float bx2 = __fmul_rn(g_boxes[o * 4 + 2], sc);
        float by2 = __fmul_rn(g_boxes[o * 4 + 3], sc);
        float w = fmaxf(__fsub_rn(bx2, bx0), 1.f);
        float h = fmaxf(__fsub_rn(by2, by0), 1.f);
        float w2 = __fmul_rn(w, 0.5f);
        float h2 = __fmul_rn(h, 0.5f);
        float xs[2] = { __fadd_rn(bx0, __fmul_rn(0.5f, w2)), __fadd_rn(bx0, __fmul_rn(1.5f, w2)) };
        float ys[2] = { __fadd_rn(by0, __fmul_rn(0.5f, h2)), __fadd_rn(by0, __fmul_rn(1.5f, h2)) };
        for (int p = 0; p < 4; ++p) {
            float y = fminf(fmaxf(ys[p >> 1], 0.f), (float)(H - 1));
            float x = fminf(fmaxf(xs[p & 1], 0.f), (float)(W - 1));
            int y0 = (int)floorf(y), x0 = (int)floorf(x);
            int y1 = min(y0 + 1, H - 1), x1 = min(x0 + 1, W - 1);
            float ly = __fsub_rn(y, (float)y0);
            float lx = __fsub_rn(x, (float)x0);
            float oly = __fsub_rn(1.f, ly);
            float olx = __fsub_rn(1.f, lx);
            s_off[l][p][0] = (y0 * W + x0) * C;
            s_off[l][p][1] = (y0 * W + x1) * C;
            s_off[l][p][2] = (y1 * W + x0) * C;
            s_off[l][p][3] = (y1 * W + x1) * C;
            s_w[l][p][0] = __fmul_rn(oly, olx);
            s_w[l][p][1] = __fmul_rn(oly, lx);
            s_w[l][p][2] = __fmul_rn(ly, olx);
            s_w[l][p][3] = __fmul_rn(ly, lx);
        }
    }
    __syncthreads();

    const float* FTb = g_feat_t + (size_t)b * PERB_FEAT;
    const int lvlOff[4] = {0, 819200, 1228800, 1433600};
    for (int u = tid; u < FDIM / 4; u += blockDim.x) {
        int l, start;
        if (u < 32)       { l = 0; start = 0;   }
        else if (u < 96)  { l = 1; start = 32;  }
        else if (u < 224) { l = 2; start = 96;  }
        else              { l = 3; start = 224; }
        const float* FT = FTb + lvlOff[l] + (u - start) * 4;
        float ax = 0.f, ay = 0.f, az = 0.f, aw = 0.f;
        #pragma unroll
        for (int p = 0; p < 4; ++p) {
            float vx = 0.f, vy = 0.f, vz = 0.f, vw = 0.f;
            #pragma unroll
            for (int t = 0; t < 4; ++t) {
                float4 v = *(const float4*)(FT + s_off[l][p][t]);
                float wv = s_w[l][p][t];
                vx = __fadd_rn(vx, __fmul_rn(wv, v.x));
                vy = __fadd_rn(vy, __fmul_rn(wv, v.y));
                vz = __fadd_rn(vz, __fmul_rn(wv, v.z));
                vw = __fadd_rn(vw, __fmul_rn(wv, v.w));
            }
            ax = __fadd_rn(ax, vx); ay = __fadd_rn(ay, vy);
            az = __fadd_rn(az, vz); aw = __fadd_rn(aw, vw);
        }
        float4 acc;
        acc.x = __fmul_rn(ax, 0.25f); acc.y = __fmul_rn(ay, 0.25f);
        acc.z = __fmul_rn(az, 0.25f); acc.w = __fmul_rn(aw, 0.25f);
        *(float4*)(frow + u * 4) = acc;
    }
}

// ---------------- stage 6: fp32 GEMM (f32x2 packed FMA) + bias + leaky ----------------
__global__ void __launch_bounds__(256) gemm_kernel(
    const float* __restrict__ Wm, const float* __restrict__ bias,
    float* __restrict__ outp, int which, int M, int Kd, int ldc, int col_off, int mulkeep)
{
    const float* A = which ? g_h1 : g_f;
    float* Cp = which ? outp : g_h1;
    __shared__ float As[16][64];
    __shared__ float Bs[16][64];
    int tid = threadIdx.x;
    int m0 = blockIdx.y << 6, n0 = blockIdx.x << 6;
    int ty = tid >> 4, tx = tid & 15;
    unsigned long long acc[4][2];
    #pragma unroll
    for (int i = 0; i < 4; ++i)
        #pragma unroll
        for (int j = 0; j < 2; ++j) acc[i][j] = f2pack(0.f, 0.f);

    int arow = m0 + (tid >> 2);
    int acol = (tid & 3) << 2;
    int asr  = tid >> 2;
    const float* aptr = A + (size_t)arow * Kd + acol;
    const float* bptr = Wm + (size_t)(tid >> 4) * HID + n0 + ((tid & 15) << 2);

    for (int kk = 0; kk < Kd; kk += 16) {
        float4 av = make_float4(0.f, 0.f, 0.f, 0.f);
        if (arow < M) av = *(const float4*)aptr;
        aptr += 16;
        As[acol + 0][asr] = av.x;
        As[acol + 1][asr] = av.y;
        As[acol + 2][asr] = av.z;
        As[acol + 3][asr] = av.w;
        *(float4*)&Bs[tid >> 4][(tid & 15) << 2] = *(const float4*)bptr;
        bptr += 16 * HID;
        __syncthreads();
        #pragma unroll
        for (int k = 0; k < 16; ++k) {
            float4 a = *(const float4*)&As[k][ty << 2];
            unsigned long long b01 = *(const unsigned long long*)&Bs[k][(tx << 2)];
            unsigned long long b23 = *(const unsigned long long*)&Bs[k][(tx << 2) + 2];
            unsigned long long a0 = f2pack(a.x, a.x);
            unsigned long long a1 = f2pack(a.y, a.y);
            unsigned long long a2 = f2pack(a.z, a.z);
            unsigned long long a3 = f2pack(a.w, a.w);
            ffma2(acc[0][0], a0, b01); ffma2(acc[0][1], a0, b23);
            ffma2(acc[1][0], a1, b01); ffma2(acc[1][1], a1, b23);
            ffma2(acc[2][0], a2, b01); ffma2(acc[2][1], a2, b23);
            ffma2(acc[3][0], a3, b01); ffma2(acc[3][1], a3, b23);
        }
        __syncthreads();
    }
    #pragma unroll
    for (int i = 0; i < 4; ++i) {
        int m = m0 + (ty << 2) + i;
        if (m >= M) continue;
        float kf = 1.f;
        if (mulkeep) kf = g_keep[m] ? 1.f : 0.f;
        float* crow = Cp + (size_t)m * ldc + col_off + n0 + (tx << 2);
        #pragma unroll
        for (int j = 0; j < 2; ++j) {
            float v0, v1;
            f2unpack(acc[i][j], v0, v1);
            int nc = n0 + (tx << 2) + (j << 1);
            v0 = __fadd_rn(v0, bias[nc]);
            v1 = __fadd_rn(v1, bias[nc + 1]);
            v0 = (v0 >= 0.f) ? v0 : __fmul_rn(v0, 0.01f);
            v1 = (v1 >= 0.f) ? v1 : __fmul_rn(v1, 0.01f);
            crow[(j << 1)]     = __fmul_rn(v0, kf);
            crow[(j << 1) + 1] = __fmul_rn(v1, kf);
        }
    }
}

// ---------------- stage 7: rescale + write bb columns (unfused) ----------------
__global__ void bbox_kernel(const float* __restrict__ orig_hw, float* __restrict__ out) {
    int idx = blockIdx.x * blockDim.x + threadIdx.x;
    if (idx >= BATCH * KDET) return;
    int b = idx / KDET;
    float oh = orig_hw[b * 2 + 0], ow = orig_hw[b * 2 + 1];
    float gain = fminf(__fdiv_rn(640.f, oh), __fdiv_rn(640.f, ow));
    float padx = __fmul_rn(__fsub_rn(640.f, __fmul_rn(ow, gain)), 0.5f);
    float pady = __fmul_rn(__fsub_rn(640.f, __fmul_rn(oh, gain)), 0.5f);
    float kf = g_keep[idx] ? 1.f : 0.f;
    const float* bx = g_boxes + (size_t)idx * 4;
    float x1 = fminf(fmaxf(__fdiv_rn(__fsub_rn(bx[0], padx), gain), 0.f), ow);
    float y1 = fminf(fmaxf(__fdiv_rn(__fsub_rn(bx[1], pady), gain), 0.f), oh);
    float x2 = fminf(fmaxf(__fdiv_rn(__fsub_rn(bx[2], padx), gain), 0.f), ow);
    float y2 = fminf(fmaxf(__fdiv_rn(__fsub_rn(bx[3], pady), gain), 0.f), oh);
    float* orow = out + (size_t)idx * 260;
    orow[0] = __fmul_rn(__fdiv_rn(x1, ow), kf);
    orow[1] = __fmul_rn(__fdiv_rn(y1, oh), kf);
    orow[2] = __fmul_rn(__fdiv_rn(x2, ow), kf);
    orow[3] = __fmul_rn(__fdiv_rn(y2, oh), kf);
}

// ---------------- launch ----------------
extern "C" void kernel_launch(void* const* d_in, const int* in_sizes, int n_in,
                              void* d_out, int out_size) {
    (void)in_sizes; (void)n_in; (void)out_size;
    const float* preds   = (const float*)d_in[0];
    const float* feat1   = (const float*)d_in[1];
    const float* feat2   = (const float*)d_in[2];
    const float* feat3   = (const float*)d_in[3];
    const float* feat4   = (const float*)d_in[4];
    const float* orig_hw = (const float*)d_in[5];
    const float* W1      = (const float*)d_in[6];
    const float* b1      = (const float*)d_in[7];
    const float* W2      = (const float*)d_in[8];
    const float* b2      = (const float*)d_in[9];
    float* out = (float*)d_out;

    // conf/argmax: 48 preds per 256-thread block (204000 / 48 = 4250 exactly)
    conf_kernel<<<(BATCH * NPRED) / PREDS_PER_BLK, 256>>>(preds);

    // fused transpose of all 4 levels
    transpose_all<<<dim3(1536, BATCH), dim3(32, 8)>>>(feat1, feat2, feat3, feat4);

    topk_kernel<<<BATCH, 1024>>>(preds);
    nms_kernel<<<BATCH, 320>>>();

    roi_kernel<<<dim3(KDET, BATCH), 256>>>();

    gemm_kernel<<<dim3(4, 38), 256>>>(W1, b1, nullptr, 0, BATCH * KDET, FDIM, HID, 0, 0);
    gemm_kernel<<<dim3(4, 38), 256>>>(W2, b2, out,     1, BATCH * KDET, HID,  260, 4, 1);

    bbox_kernel<<<(BATCH * KDET + 255) / 256, 256>>>(orig_hw, out);
}